// round 2
// baseline (speedup 1.0000x reference)
#include <cuda_runtime.h>
#include <cstdint>

// Table-batched embedding bag, SUM pooling.
// indices: int32 [T*B*L] (table-local row ids)  -- JAX x64-disabled downcasts int64->int32
// offsets: int32 [T*B+1] (CSR bag offsets)
// weights: fp32 [T*E, D=128] stacked tables
// hash_size_cumsum: int32 [T+1] per-table base row
// out: fp32 [B, T*D]
//
// One warp per bag. Each lane holds one float4 of the D=128 row (32*4=128).
// 2x unrolled gather loop for memory-level parallelism.

#define EMB_D 128

__global__ void __launch_bounds__(256) tbe_fwd_kernel(
    const int*   __restrict__ indices,
    const int*   __restrict__ offsets,
    const float* __restrict__ weights,
    const int*   __restrict__ hsc,
    float*       __restrict__ out,
    int batch, int n_tables, int num_bags)
{
    const int warp_global = (blockIdx.x * blockDim.x + threadIdx.x) >> 5;
    const int lane = threadIdx.x & 31;
    if (warp_global >= num_bags) return;

    const int seg   = warp_global;
    const int table = seg / batch;
    const int b     = seg - table * batch;

    const long long base  = (long long)hsc[table];
    const int start = offsets[seg];
    const int end   = offsets[seg + 1];

    float4 acc = make_float4(0.f, 0.f, 0.f, 0.f);

    int j = start;
    // 2x unroll: two independent row gathers in flight
    for (; j + 1 < end; j += 2) {
        const long long lin0 = (long long)indices[j]     + base;
        const long long lin1 = (long long)indices[j + 1] + base;
        const float4* r0 = reinterpret_cast<const float4*>(weights + lin0 * EMB_D);
        const float4* r1 = reinterpret_cast<const float4*>(weights + lin1 * EMB_D);
        float4 v0 = __ldg(r0 + lane);
        float4 v1 = __ldg(r1 + lane);
        acc.x += v0.x; acc.y += v0.y; acc.z += v0.z; acc.w += v0.w;
        acc.x += v1.x; acc.y += v1.y; acc.z += v1.z; acc.w += v1.w;
    }
    if (j < end) {
        const long long lin = (long long)indices[j] + base;
        const float4* r = reinterpret_cast<const float4*>(weights + lin * EMB_D);
        float4 v = __ldg(r + lane);
        acc.x += v.x; acc.y += v.y; acc.z += v.z; acc.w += v.w;
    }

    // out[b, table*D + lane*4 .. +3]
    float4* o = reinterpret_cast<float4*>(
        out + (size_t)b * ((size_t)n_tables * EMB_D) + (size_t)table * EMB_D);
    o[lane] = acc;
}

extern "C" void kernel_launch(void* const* d_in, const int* in_sizes, int n_in,
                              void* d_out, int out_size)
{
    const int*   indices = (const int*)d_in[0];
    const int*   offsets = (const int*)d_in[1];
    const float* weights = (const float*)d_in[2];
    const int*   hsc     = (const int*)d_in[3];
    float* out = (float*)d_out;

    const int num_bags = in_sizes[1] - 1;   // T*B
    const int n_tables = in_sizes[3] - 1;   // T
    const int batch    = num_bags / n_tables;

    const int warps_per_block = 8;          // 256 threads
    const int blocks = (num_bags + warps_per_block - 1) / warps_per_block;

    tbe_fwd_kernel<<<blocks, warps_per_block * 32>>>(
        indices, offsets, weights, hsc, out, batch, n_tables, num_bags);
}

// round 3
// speedup vs baseline: 1.0075x; 1.0075x over previous
#include <cuda_runtime.h>
#include <cstdint>

// Table-batched embedding bag, SUM pooling.
// indices: int32 [T*B*L], offsets: int32 [T*B+1], weights: fp32 [T*E, 128],
// hash_size_cumsum: int32 [T+1], out: fp32 [B, T*128]
//
// One warp per bag; lane = one float4 of the 128-wide row.
// Bag indices are prefetched with a single lane-parallel coalesced load and
// distributed via shuffle, so all row gathers are issue-independent.
// 4x unrolled gather with 4 accumulators for high memory-level parallelism.

#define EMB_D 128

__global__ void __launch_bounds__(256) tbe_fwd_kernel(
    const int*   __restrict__ indices,
    const int*   __restrict__ offsets,
    const float* __restrict__ weights,
    const int*   __restrict__ hsc,
    float*       __restrict__ out,
    int batch, int n_tables, int num_bags)
{
    const int warp_global = (blockIdx.x * blockDim.x + threadIdx.x) >> 5;
    const int lane = threadIdx.x & 31;
    if (warp_global >= num_bags) return;

    const int seg   = warp_global;
    const int table = seg / batch;
    const int b     = seg - table * batch;

    const long long base  = (long long)hsc[table];
    const int start = offsets[seg];
    const int end   = offsets[seg + 1];

    float4 a0 = make_float4(0.f, 0.f, 0.f, 0.f);
    float4 a1 = make_float4(0.f, 0.f, 0.f, 0.f);
    float4 a2 = make_float4(0.f, 0.f, 0.f, 0.f);
    float4 a3 = make_float4(0.f, 0.f, 0.f, 0.f);

    for (int chunk = start; chunk < end; chunk += 32) {
        const int cnt = min(32, end - chunk);
        // one coalesced index load for the whole chunk
        int myidx = (lane < cnt) ? indices[chunk + lane] : 0;

        int k = 0;
        for (; k + 3 < cnt; k += 4) {
            const long long l0 = (long long)__shfl_sync(0xffffffffu, myidx, k)     + base;
            const long long l1 = (long long)__shfl_sync(0xffffffffu, myidx, k + 1) + base;
            const long long l2 = (long long)__shfl_sync(0xffffffffu, myidx, k + 2) + base;
            const long long l3 = (long long)__shfl_sync(0xffffffffu, myidx, k + 3) + base;
            const float4 v0 = __ldg(reinterpret_cast<const float4*>(weights + l0 * EMB_D) + lane);
            const float4 v1 = __ldg(reinterpret_cast<const float4*>(weights + l1 * EMB_D) + lane);
            const float4 v2 = __ldg(reinterpret_cast<const float4*>(weights + l2 * EMB_D) + lane);
            const float4 v3 = __ldg(reinterpret_cast<const float4*>(weights + l3 * EMB_D) + lane);
            a0.x += v0.x; a0.y += v0.y; a0.z += v0.z; a0.w += v0.w;
            a1.x += v1.x; a1.y += v1.y; a1.z += v1.z; a1.w += v1.w;
            a2.x += v2.x; a2.y += v2.y; a2.z += v2.z; a2.w += v2.w;
            a3.x += v3.x; a3.y += v3.y; a3.z += v3.z; a3.w += v3.w;
        }
        for (; k < cnt; k++) {
            const long long l = (long long)__shfl_sync(0xffffffffu, myidx, k) + base;
            const float4 v = __ldg(reinterpret_cast<const float4*>(weights + l * EMB_D) + lane);
            a0.x += v.x; a0.y += v.y; a0.z += v.z; a0.w += v.w;
        }
    }

    float4 acc;
    acc.x = (a0.x + a1.x) + (a2.x + a3.x);
    acc.y = (a0.y + a1.y) + (a2.y + a3.y);
    acc.z = (a0.z + a1.z) + (a2.z + a3.z);
    acc.w = (a0.w + a1.w) + (a2.w + a3.w);

    float4* o = reinterpret_cast<float4*>(
        out + (size_t)b * ((size_t)n_tables * EMB_D) + (size_t)table * EMB_D);
    o[lane] = acc;
}

extern "C" void kernel_launch(void* const* d_in, const int* in_sizes, int n_in,
                              void* d_out, int out_size)
{
    const int*   indices = (const int*)d_in[0];
    const int*   offsets = (const int*)d_in[1];
    const float* weights = (const float*)d_in[2];
    const int*   hsc     = (const int*)d_in[3];
    float* out = (float*)d_out;

    const int num_bags = in_sizes[1] - 1;   // T*B
    const int n_tables = in_sizes[3] - 1;   // T
    const int batch    = num_bags / n_tables;

    const int warps_per_block = 8;          // 256 threads
    const int blocks = (num_bags + warps_per_block - 1) / warps_per_block;

    tbe_fwd_kernel<<<blocks, warps_per_block * 32>>>(
        indices, offsets, weights, hsc, out, batch, n_tables, num_bags);
}